// round 11
// baseline (speedup 1.0000x reference)
#include <cuda_runtime.h>
#include <cuda_bf16.h>
#include <cstdint>

// ---------------- problem constants ----------------
#define NROWS 8192
#define DDIM  768

// ---------------- GEMM tiling ----------------
#define BM 128             // CTA tile m
#define BN 128             // CTA tile n
#define BK 32              // k per chunk
#define NKT (DDIM / BK)    // 24 chunks
#define NMB (NROWS / BM)   // 64
#define NNB (NROWS / BN)   // 64
#define NSTG 6             // ring stages per matrix

// smem: XOR-swizzled rows of 64B, no padding
#define ROW_B 64
#define A_STG (BM * ROW_B)                 // 8192
#define B_STG (BN * ROW_B)                 // 8192
#define OFF_A 0
#define OFF_B (NSTG * A_STG)               // 49152
#define OFF_RED (OFF_B + NSTG * B_STG)     // 98304
#define SMEM_TOTAL (OFF_RED + 2 * BM * 4)  // 99328

// ---------------- device scratch ----------------
__device__ __nv_bfloat16 g_exn[NROWS * DDIM];
__device__ __nv_bfloat16 g_eyn[NROWS * DDIM];

// ---------------- PTX helpers ----------------
__device__ __forceinline__ uint32_t s2u(const void* p) {
    uint32_t a;
    asm("{ .reg .u64 t; cvta.to.shared.u64 t, %1; cvt.u32.u64 %0, t; }" : "=r"(a) : "l"(p));
    return a;
}
__device__ __forceinline__ void cpa16(uint32_t dst, const void* src) {
    asm volatile("cp.async.cg.shared.global [%0], [%1], 16;" :: "r"(dst), "l"(src));
}
__device__ __forceinline__ void cpa_commit() { asm volatile("cp.async.commit_group;"); }
__device__ __forceinline__ void cpa_wait1()  { asm volatile("cp.async.wait_group 1;"); }
__device__ __forceinline__ void ldsm4(uint32_t (&r)[4], uint32_t addr) {
    asm volatile("ldmatrix.sync.aligned.m8n8.x4.shared.b16 {%0,%1,%2,%3}, [%4];"
                 : "=r"(r[0]), "=r"(r[1]), "=r"(r[2]), "=r"(r[3]) : "r"(addr));
}
__device__ __forceinline__ void mma16816(float (&c)[4], const uint32_t (&a)[4],
                                         uint32_t b0, uint32_t b1) {
    asm volatile(
        "mma.sync.aligned.m16n8k16.row.col.f32.bf16.bf16.f32 "
        "{%0,%1,%2,%3}, {%4,%5,%6,%7}, {%8,%9}, {%0,%1,%2,%3};"
        : "+f"(c[0]), "+f"(c[1]), "+f"(c[2]), "+f"(c[3])
        : "r"(a[0]), "r"(a[1]), "r"(a[2]), "r"(a[3]), "r"(b0), "r"(b1));
}

// ---------------------------------------------------------------------------
// out init (harness poisons to 0xAA; atomics need 0.0f start)
// ---------------------------------------------------------------------------
__global__ void init_out_kernel(float* __restrict__ out) {
    out[blockIdx.x * 256 + threadIdx.x] = 0.0f;
}

// ---------------------------------------------------------------------------
// Row L2-normalize fp32 -> bf16 for BOTH matrices in one launch.
// grid 2048: blocks [0,1024) -> ex, [1024,2048) -> ey. Warp per row.
// ---------------------------------------------------------------------------
__global__ __launch_bounds__(256) void normalize_kernel(const float* __restrict__ ex,
                                                        const float* __restrict__ ey) {
    const int half = blockIdx.x >> 10;
    const float* in = half ? ey : ex;
    __nv_bfloat16* outg = half ? g_eyn : g_exn;
    const int w = threadIdx.x >> 5;
    const int lane = threadIdx.x & 31;
    const int row = (blockIdx.x & 1023) * 8 + w;

    const float4* p = (const float4*)(in + (size_t)row * DDIM);
    float4 v[6];
    float s = 0.f;
#pragma unroll
    for (int j = 0; j < 6; j++) {
        v[j] = p[lane + j * 32];
        s += v[j].x * v[j].x + v[j].y * v[j].y + v[j].z * v[j].z + v[j].w * v[j].w;
    }
#pragma unroll
    for (int o = 16; o; o >>= 1) s += __shfl_xor_sync(0xffffffffu, s, o);
    const float inv = 1.0f / fmaxf(sqrtf(s), 1e-8f);

    uint4* q = (uint4*)(outg + (size_t)row * DDIM);
#pragma unroll
    for (int j = 0; j < 3; j++) {
        const float4 a = v[2 * j], b = v[2 * j + 1];
        __nv_bfloat162 p0 = __floats2bfloat162_rn(a.x * inv, a.y * inv);
        __nv_bfloat162 p1 = __floats2bfloat162_rn(a.z * inv, a.w * inv);
        __nv_bfloat162 p2 = __floats2bfloat162_rn(b.x * inv, b.y * inv);
        __nv_bfloat162 p3 = __floats2bfloat162_rn(b.z * inv, b.w * inv);
        uint4 o;
        o.x = *(uint32_t*)&p0; o.y = *(uint32_t*)&p1;
        o.z = *(uint32_t*)&p2; o.w = *(uint32_t*)&p3;
        q[lane + j * 32] = o;
    }
}

// ---------------------------------------------------------------------------
// Fused GEMM (exn @ eyn^T) + row-max. CTA 128 threads, 4 warps as 2x2,
// warp tile 64x64, 6-stage XOR-swizzled ring, 2 CTAs/SM.
// Swizzle key = (row>>1)&3 (64B rows: 2 rows per 128B line).
// ---------------------------------------------------------------------------
__global__ __launch_bounds__(128, 2) void chamfer_kernel(float* __restrict__ out) {
    extern __shared__ char smem[];
    const uint32_t sb = s2u(smem);
    float* red = (float*)(smem + OFF_RED);

    const int tid = threadIdx.x;
    const int lane = tid & 31;
    const int wid = tid >> 5;      // 0..3
    const int wm = wid >> 1;       // 0..1 -> m offset wm*64
    const int wn = wid & 1;        // 0..1 -> n offset wn*64
    const int g = lane >> 2;
    const int tig = lane & 3;

    const int m = blockIdx.x >> 6;
    const int n = blockIdx.x & 63;
    const __nv_bfloat16* Ag = g_exn + (size_t)m * BM * DDIM;
    const __nv_bfloat16* Bg = g_eyn + (size_t)n * BN * DDIM;

    // ---- writer addressing: 1 thread per row (128 rows), 4 x 16B units each ----
    const int l_key = (tid >> 1) & 3;
    const uint32_t wA0 = sb + OFF_A + tid * ROW_B;
    const uint32_t wB0 = sb + OFF_B + tid * ROW_B;
    const __nv_bfloat16* gA0 = Ag + (size_t)tid * DDIM;
    const __nv_bfloat16* gB0 = Bg + (size_t)tid * DDIM;

    auto issue = [&](int chunk, int stage) {
        if (chunk < NKT) {
            const __nv_bfloat16* sa = gA0 + chunk * BK;
            const __nv_bfloat16* sbp = gB0 + chunk * BK;
            const uint32_t da = wA0 + stage * A_STG;
            const uint32_t db = wB0 + stage * B_STG;
#pragma unroll
            for (int j = 0; j < 4; j++) {
                cpa16(da + ((j ^ l_key) * 16), sa + j * 8);
                cpa16(db + ((j ^ l_key) * 16), sbp + j * 8);
            }
        }
    };

    // ---- reader addressing (swizzle folded into base; kk toggle = XOR 32) ----
    const int lrow = lane & 15;
    const int h = lane >> 4;
    const uint32_t cx0 = ((h ^ ((lrow >> 1) & 3)) * 16);
    const uint32_t aBase = sb + OFF_A + (wm * 64 + lrow) * ROW_B + cx0;
    const uint32_t bBase = sb + OFF_B + (wn * 64 + lrow) * ROW_B + cx0;

    float acc[4][8][4];
#pragma unroll
    for (int mt = 0; mt < 4; mt++)
#pragma unroll
        for (int n8 = 0; n8 < 8; n8++)
#pragma unroll
            for (int r = 0; r < 4; r++) acc[mt][n8][r] = 0.f;

    auto compute = [&](int stage) {
#pragma unroll
        for (int kk = 0; kk < 2; ++kk) {
            uint32_t a[4][4], b[4][4];
#pragma unroll
            for (int mt = 0; mt < 4; mt++)
                ldsm4(a[mt], (aBase + stage * A_STG + mt * 1024) ^ (kk * 32));
#pragma unroll
            for (int n16 = 0; n16 < 4; n16++)
                ldsm4(b[n16], (bBase + stage * B_STG + n16 * 1024) ^ (kk * 32));
#pragma unroll
            for (int mt = 0; mt < 4; mt++)
#pragma unroll
                for (int n8 = 0; n8 < 8; n8++) {
                    const int n16 = n8 >> 1, sub = n8 & 1;
                    mma16816(acc[mt][n8], a[mt], b[n16][sub], b[n16][sub + 2]);
                }
        }
    };

    // prologue: 2 groups of 2 chunks (4 chunks in flight)
    issue(0, 0); issue(1, 1); cpa_commit();
    issue(2, 2); issue(3, 3); cpa_commit();

    // 12 supersteps, stage pattern period 3 -> unroll 3 (constant stages)
#pragma unroll 1
    for (int jo = 0; jo < 4; ++jo) {
        const int c0 = jo * 6;
        cpa_wait1(); __syncthreads();
        issue(c0 + 4, 4); issue(c0 + 5, 5); cpa_commit();
        compute(0); compute(1);
        cpa_wait1(); __syncthreads();
        issue(c0 + 6, 0); issue(c0 + 7, 1); cpa_commit();
        compute(2); compute(3);
        cpa_wait1(); __syncthreads();
        issue(c0 + 8, 2); issue(c0 + 9, 3); cpa_commit();
        compute(4); compute(5);
    }

    // ---- row-max epilogue ----
    float rm[4][2];
#pragma unroll
    for (int mt = 0; mt < 4; mt++) {
        float m0 = -1e30f, m1 = -1e30f;
#pragma unroll
        for (int n8 = 0; n8 < 8; n8++) {
            m0 = fmaxf(m0, fmaxf(acc[mt][n8][0], acc[mt][n8][1]));
            m1 = fmaxf(m1, fmaxf(acc[mt][n8][2], acc[mt][n8][3]));
        }
        rm[mt][0] = m0; rm[mt][1] = m1;
    }
    __syncthreads();
#pragma unroll
    for (int mt = 0; mt < 4; mt++) {
#pragma unroll
        for (int hh = 0; hh < 2; hh++) {
            float v = rm[mt][hh];
            v = fmaxf(v, __shfl_xor_sync(0xffffffffu, v, 1));
            v = fmaxf(v, __shfl_xor_sync(0xffffffffu, v, 2));
            if (tig == 0)
                red[wn * BM + wm * 64 + mt * 16 + hh * 8 + g] = v;
        }
    }
    __syncthreads();
    {
        const float v = fmaxf(red[tid], red[BM + tid]);
        atomicMax((int*)&out[m * BM + tid], __float_as_int(v));
    }
}

// ---------------------------------------------------------------------------
// launch
// ---------------------------------------------------------------------------
extern "C" void kernel_launch(void* const* d_in, const int* in_sizes, int n_in,
                              void* d_out, int out_size) {
    const float* ex = (const float*)d_in[0];
    const float* ey = (const float*)d_in[1];
    float* out = (float*)d_out;

    cudaFuncSetAttribute(chamfer_kernel, cudaFuncAttributeMaxDynamicSharedMemorySize,
                         SMEM_TOTAL);

    init_out_kernel<<<NROWS / 256, 256>>>(out);
    normalize_kernel<<<2048, 256>>>(ex, ey);
    chamfer_kernel<<<NMB * NNB, 128, SMEM_TOTAL>>>(out);
}

// round 12
// speedup vs baseline: 1.0511x; 1.0511x over previous
#include <cuda_runtime.h>
#include <cuda_bf16.h>
#include <cstdint>

// ---------------- problem constants ----------------
#define NROWS 8192
#define DDIM  768

// ---------------- GEMM tiling ----------------
#define BM 128             // CTA tile m
#define BN 128             // CTA tile n
#define BK 32              // k per chunk
#define NKT (DDIM / BK)    // 24 chunks
#define NMB (NROWS / BM)   // 64
#define NNB (NROWS / BN)   // 64
#define NSTG 4             // ring stages per matrix

// smem: XOR-swizzled rows of 64B, no padding
#define ROW_B 64
#define A_STG (BM * ROW_B)                 // 8192
#define B_STG (BN * ROW_B)                 // 8192
#define OFF_A 0
#define OFF_B (NSTG * A_STG)               // 32768
#define OFF_RED (OFF_B + NSTG * B_STG)     // 65536
#define SMEM_TOTAL (OFF_RED + 2 * BM * 4)  // 66560 -> 3 CTAs/SM

// ---------------- device scratch ----------------
__device__ __nv_bfloat16 g_exn[NROWS * DDIM];
__device__ __nv_bfloat16 g_eyn[NROWS * DDIM];

// ---------------- PTX helpers ----------------
__device__ __forceinline__ uint32_t s2u(const void* p) {
    uint32_t a;
    asm("{ .reg .u64 t; cvta.to.shared.u64 t, %1; cvt.u32.u64 %0, t; }" : "=r"(a) : "l"(p));
    return a;
}
__device__ __forceinline__ void cpa16(uint32_t dst, const void* src) {
    asm volatile("cp.async.cg.shared.global [%0], [%1], 16;" :: "r"(dst), "l"(src));
}
__device__ __forceinline__ void cpa_commit() { asm volatile("cp.async.commit_group;"); }
__device__ __forceinline__ void cpa_wait2()  { asm volatile("cp.async.wait_group 2;"); }
__device__ __forceinline__ void ldsm4(uint32_t (&r)[4], uint32_t addr) {
    asm volatile("ldmatrix.sync.aligned.m8n8.x4.shared.b16 {%0,%1,%2,%3}, [%4];"
                 : "=r"(r[0]), "=r"(r[1]), "=r"(r[2]), "=r"(r[3]) : "r"(addr));
}
__device__ __forceinline__ void mma16816(float (&c)[4], const uint32_t (&a)[4],
                                         uint32_t b0, uint32_t b1) {
    asm volatile(
        "mma.sync.aligned.m16n8k16.row.col.f32.bf16.bf16.f32 "
        "{%0,%1,%2,%3}, {%4,%5,%6,%7}, {%8,%9}, {%0,%1,%2,%3};"
        : "+f"(c[0]), "+f"(c[1]), "+f"(c[2]), "+f"(c[3])
        : "r"(a[0]), "r"(a[1]), "r"(a[2]), "r"(a[3]), "r"(b0), "r"(b1));
}

// ---------------------------------------------------------------------------
// out init (harness poisons to 0xAA; atomics need 0.0f start)
// ---------------------------------------------------------------------------
__global__ void init_out_kernel(float* __restrict__ out) {
    out[blockIdx.x * 256 + threadIdx.x] = 0.0f;
}

// ---------------------------------------------------------------------------
// Row L2-normalize fp32 -> bf16 for BOTH matrices in one launch.
// grid 2048: blocks [0,1024) -> ex, [1024,2048) -> ey. Warp per row.
// ---------------------------------------------------------------------------
__global__ __launch_bounds__(256) void normalize_kernel(const float* __restrict__ ex,
                                                        const float* __restrict__ ey) {
    const int half = blockIdx.x >> 10;
    const float* in = half ? ey : ex;
    __nv_bfloat16* outg = half ? g_eyn : g_exn;
    const int w = threadIdx.x >> 5;
    const int lane = threadIdx.x & 31;
    const int row = (blockIdx.x & 1023) * 8 + w;

    const float4* p = (const float4*)(in + (size_t)row * DDIM);
    float4 v[6];
    float s = 0.f;
#pragma unroll
    for (int j = 0; j < 6; j++) {
        v[j] = p[lane + j * 32];
        s += v[j].x * v[j].x + v[j].y * v[j].y + v[j].z * v[j].z + v[j].w * v[j].w;
    }
#pragma unroll
    for (int o = 16; o; o >>= 1) s += __shfl_xor_sync(0xffffffffu, s, o);
    const float inv = 1.0f / fmaxf(sqrtf(s), 1e-8f);

    uint4* q = (uint4*)(outg + (size_t)row * DDIM);
#pragma unroll
    for (int j = 0; j < 3; j++) {
        const float4 a = v[2 * j], b = v[2 * j + 1];
        __nv_bfloat162 p0 = __floats2bfloat162_rn(a.x * inv, a.y * inv);
        __nv_bfloat162 p1 = __floats2bfloat162_rn(a.z * inv, a.w * inv);
        __nv_bfloat162 p2 = __floats2bfloat162_rn(b.x * inv, b.y * inv);
        __nv_bfloat162 p3 = __floats2bfloat162_rn(b.z * inv, b.w * inv);
        uint4 o;
        o.x = *(uint32_t*)&p0; o.y = *(uint32_t*)&p1;
        o.z = *(uint32_t*)&p2; o.w = *(uint32_t*)&p3;
        q[lane + j * 32] = o;
    }
}

// ---------------------------------------------------------------------------
// Fused GEMM (exn @ eyn^T) + row-max. CTA 128 threads, 4 warps as 2x2,
// warp tile 64x64, 4-stage XOR-swizzled ring (3 chunks ahead), 3 CTAs/SM.
// Swizzle key = (row>>1)&3 (64B rows: 2 rows per 128B line).
// ---------------------------------------------------------------------------
__global__ __launch_bounds__(128, 3) void chamfer_kernel(float* __restrict__ out) {
    extern __shared__ char smem[];
    const uint32_t sb = s2u(smem);
    float* red = (float*)(smem + OFF_RED);

    const int tid = threadIdx.x;
    const int lane = tid & 31;
    const int wid = tid >> 5;      // 0..3
    const int wm = wid >> 1;       // 0..1 -> m offset wm*64
    const int wn = wid & 1;        // 0..1 -> n offset wn*64
    const int g = lane >> 2;
    const int tig = lane & 3;

    const int m = blockIdx.x >> 6;
    const int n = blockIdx.x & 63;
    const __nv_bfloat16* Ag = g_exn + (size_t)m * BM * DDIM;
    const __nv_bfloat16* Bg = g_eyn + (size_t)n * BN * DDIM;

    // ---- writer addressing: 1 thread per row (128 rows), 4 x 16B units each ----
    const int l_key = (tid >> 1) & 3;
    const uint32_t wA0 = sb + OFF_A + tid * ROW_B;
    const uint32_t wB0 = sb + OFF_B + tid * ROW_B;
    const __nv_bfloat16* gA0 = Ag + (size_t)tid * DDIM;
    const __nv_bfloat16* gB0 = Bg + (size_t)tid * DDIM;

    auto issue = [&](int chunk) {
        if (chunk < NKT) {
            const int stage = chunk & 3;
            const __nv_bfloat16* sa = gA0 + chunk * BK;
            const __nv_bfloat16* sbp = gB0 + chunk * BK;
            const uint32_t da = wA0 + stage * A_STG;
            const uint32_t db = wB0 + stage * B_STG;
#pragma unroll
            for (int j = 0; j < 4; j++) {
                cpa16(da + ((j ^ l_key) * 16), sa + j * 8);
                cpa16(db + ((j ^ l_key) * 16), sbp + j * 8);
            }
        }
    };

    // ---- reader addressing (swizzle folded into base; kk toggle = XOR 32) ----
    const int lrow = lane & 15;
    const int h = lane >> 4;
    const uint32_t cx0 = ((h ^ ((lrow >> 1) & 3)) * 16);
    const uint32_t aBase = sb + OFF_A + (wm * 64 + lrow) * ROW_B + cx0;
    const uint32_t bBase = sb + OFF_B + (wn * 64 + lrow) * ROW_B + cx0;

    float acc[4][8][4];
#pragma unroll
    for (int mt = 0; mt < 4; mt++)
#pragma unroll
        for (int n8 = 0; n8 < 8; n8++)
#pragma unroll
            for (int r = 0; r < 4; r++) acc[mt][n8][r] = 0.f;

    // compute one chunk; A fragment loaded per-mt to minimize live registers
    auto compute = [&](int stage) {
#pragma unroll
        for (int kk = 0; kk < 2; ++kk) {
            uint32_t b[4][4];
#pragma unroll
            for (int n16 = 0; n16 < 4; n16++)
                ldsm4(b[n16], (bBase + stage * B_STG + n16 * 1024) ^ (kk * 32));
#pragma unroll
            for (int mt = 0; mt < 4; mt++) {
                uint32_t a[4];
                ldsm4(a, (aBase + stage * A_STG + mt * 1024) ^ (kk * 32));
#pragma unroll
                for (int n8 = 0; n8 < 8; n8++) {
                    const int n16 = n8 >> 1, sub = n8 & 1;
                    mma16816(acc[mt][n8], a, b[n16][sub], b[n16][sub + 2]);
                }
            }
        }
    };

    // prologue: 3 chunks in flight
    issue(0); cpa_commit();
    issue(1); cpa_commit();
    issue(2); cpa_commit();

#pragma unroll 1
    for (int kt = 0; kt < NKT; ++kt) {
        cpa_wait2();          // chunk kt landed (3 groups max in flight)
        __syncthreads();      // readers done with stage (kt+3)&3 from chunk kt-1
        issue(kt + 3);        // write stage (kt+3)&3  (!= kt&3)
        cpa_commit();         // uniform group counting (empty near tail)
        compute(kt & 3);
    }

    // ---- row-max epilogue ----
    float rm[4][2];
#pragma unroll
    for (int mt = 0; mt < 4; mt++) {
        float m0 = -1e30f, m1 = -1e30f;
#pragma unroll
        for (int n8 = 0; n8 < 8; n8++) {
            m0 = fmaxf(m0, fmaxf(acc[mt][n8][0], acc[mt][n8][1]));
            m1 = fmaxf(m1, fmaxf(acc[mt][n8][2], acc[mt][n8][3]));
        }
        rm[mt][0] = m0; rm[mt][1] = m1;
    }
    __syncthreads();
#pragma unroll
    for (int mt = 0; mt < 4; mt++) {
#pragma unroll
        for (int hh = 0; hh < 2; hh++) {
            float v = rm[mt][hh];
            v = fmaxf(v, __shfl_xor_sync(0xffffffffu, v, 1));
            v = fmaxf(v, __shfl_xor_sync(0xffffffffu, v, 2));
            if (tig == 0)
                red[wn * BM + wm * 64 + mt * 16 + hh * 8 + g] = v;
        }
    }
    __syncthreads();
    {
        const float v = fmaxf(red[tid], red[BM + tid]);
        atomicMax((int*)&out[m * BM + tid], __float_as_int(v));
    }
}

// ---------------------------------------------------------------------------
// launch
// ---------------------------------------------------------------------------
extern "C" void kernel_launch(void* const* d_in, const int* in_sizes, int n_in,
                              void* d_out, int out_size) {
    const float* ex = (const float*)d_in[0];
    const float* ey = (const float*)d_in[1];
    float* out = (float*)d_out;

    cudaFuncSetAttribute(chamfer_kernel, cudaFuncAttributeMaxDynamicSharedMemorySize,
                         SMEM_TOTAL);

    init_out_kernel<<<NROWS / 256, 256>>>(out);
    normalize_kernel<<<2048, 256>>>(ex, ey);
    chamfer_kernel<<<NMB * NNB, 128, SMEM_TOTAL>>>(out);
}

// round 13
// speedup vs baseline: 1.5509x; 1.4755x over previous
#include <cuda_runtime.h>
#include <cuda_bf16.h>
#include <cstdint>

// ---------------- problem constants ----------------
#define NROWS 8192
#define DDIM  768

// ---------------- GEMM tiling ----------------
#define BM 128             // CTA tile m
#define BN 128             // CTA tile n
#define BK 32              // k per chunk
#define NKT (DDIM / BK)    // 24 chunks
#define NMB (NROWS / BM)   // 64
#define NNB (NROWS / BN)   // 64
#define NSTG 6             // ring stages per matrix

// smem: XOR-swizzled rows of 64B, no padding
#define ROW_B 64
#define STAGE_B (BM * ROW_B)              // 8192
#define OFF_A 0
#define OFF_B (NSTG * STAGE_B)            // 49152
#define OFF_RED (OFF_B + NSTG * STAGE_B)  // 98304
#define SMEM_TOTAL (OFF_RED + 2 * BM * 4) // 99328

// ---------------- device scratch ----------------
__device__ __nv_bfloat16 g_exn[NROWS * DDIM];
__device__ __nv_bfloat16 g_eyn[NROWS * DDIM];

// ---------------- PTX helpers ----------------
__device__ __forceinline__ uint32_t s2u(const void* p) {
    uint32_t a;
    asm("{ .reg .u64 t; cvta.to.shared.u64 t, %1; cvt.u32.u64 %0, t; }" : "=r"(a) : "l"(p));
    return a;
}
__device__ __forceinline__ void cpa16(uint32_t dst, const void* src) {
    asm volatile("cp.async.cg.shared.global [%0], [%1], 16;" :: "r"(dst), "l"(src));
}
__device__ __forceinline__ void cpa_commit() { asm volatile("cp.async.commit_group;"); }
__device__ __forceinline__ void cpa_wait1()  { asm volatile("cp.async.wait_group 1;"); }
__device__ __forceinline__ void ldsm4(uint32_t (&r)[4], uint32_t addr) {
    asm volatile("ldmatrix.sync.aligned.m8n8.x4.shared.b16 {%0,%1,%2,%3}, [%4];"
                 : "=r"(r[0]), "=r"(r[1]), "=r"(r[2]), "=r"(r[3]) : "r"(addr));
}
__device__ __forceinline__ void mma16816(float (&c)[4], const uint32_t (&a)[4],
                                         uint32_t b0, uint32_t b1) {
    asm volatile(
        "mma.sync.aligned.m16n8k16.row.col.f32.bf16.bf16.f32 "
        "{%0,%1,%2,%3}, {%4,%5,%6,%7}, {%8,%9}, {%0,%1,%2,%3};"
        : "+f"(c[0]), "+f"(c[1]), "+f"(c[2]), "+f"(c[3])
        : "r"(a[0]), "r"(a[1]), "r"(a[2]), "r"(a[3]), "r"(b0), "r"(b1));
}

// ---------------------------------------------------------------------------
// Row L2-normalize fp32 -> bf16 for BOTH matrices + zero-init out (fused).
// grid 2048: blocks [0,1024) -> ex, [1024,2048) -> ey. Warp per row.
// Blocks 0..31 additionally zero the 8192-element output (atomicMax base).
// ---------------------------------------------------------------------------
__global__ __launch_bounds__(256) void normalize_kernel(const float* __restrict__ ex,
                                                        const float* __restrict__ ey,
                                                        float* __restrict__ out) {
    if (blockIdx.x < 32) out[blockIdx.x * 256 + threadIdx.x] = 0.0f;

    const int half = blockIdx.x >> 10;
    const float* in = half ? ey : ex;
    __nv_bfloat16* outg = half ? g_eyn : g_exn;
    const int w = threadIdx.x >> 5;
    const int lane = threadIdx.x & 31;
    const int row = (blockIdx.x & 1023) * 8 + w;

    const float4* p = (const float4*)(in + (size_t)row * DDIM);
    float4 v[6];
    float s = 0.f;
#pragma unroll
    for (int j = 0; j < 6; j++) {
        v[j] = p[lane + j * 32];
        s += v[j].x * v[j].x + v[j].y * v[j].y + v[j].z * v[j].z + v[j].w * v[j].w;
    }
#pragma unroll
    for (int o = 16; o; o >>= 1) s += __shfl_xor_sync(0xffffffffu, s, o);
    const float inv = 1.0f / fmaxf(sqrtf(s), 1e-8f);

    uint4* q = (uint4*)(outg + (size_t)row * DDIM);
#pragma unroll
    for (int j = 0; j < 3; j++) {
        const float4 a = v[2 * j], b = v[2 * j + 1];
        __nv_bfloat162 p0 = __floats2bfloat162_rn(a.x * inv, a.y * inv);
        __nv_bfloat162 p1 = __floats2bfloat162_rn(a.z * inv, a.w * inv);
        __nv_bfloat162 p2 = __floats2bfloat162_rn(b.x * inv, b.y * inv);
        __nv_bfloat162 p3 = __floats2bfloat162_rn(b.z * inv, b.w * inv);
        uint4 o;
        o.x = *(uint32_t*)&p0; o.y = *(uint32_t*)&p1;
        o.z = *(uint32_t*)&p2; o.w = *(uint32_t*)&p3;
        q[lane + j * 32] = o;
    }
}

// ---------------------------------------------------------------------------
// Fused GEMM (exn @ eyn^T) + row-max. XOR-swizzled 6-stage ring, barrier per
// 2 chunks, 2 CTAs/SM. grid 64x64; warp grid 4x2; warp tile 32x64.
// Swizzle key = (row>>1)&3. Odd CTAs delay ~half a superstep to force the
// two co-resident CTAs into anti-phase (overlap smem-port and tensor phases).
// ---------------------------------------------------------------------------
__global__ __launch_bounds__(256, 2) void chamfer_kernel(float* __restrict__ out) {
    extern __shared__ char smem[];
    const uint32_t sb = s2u(smem);
    float* red = (float*)(smem + OFF_RED);

    const int tid = threadIdx.x;
    const int lane = tid & 31;
    const int wid = tid >> 5;
    const int wm = wid >> 1;   // 0..3
    const int wn = wid & 1;    // 0..1
    const int g = lane >> 2;
    const int tig = lane & 3;

    // anti-phase seed for co-resident CTA pairs
    if (blockIdx.x & 1) __nanosleep(450);

    const int m = blockIdx.x >> 6;
    const int n = blockIdx.x & 63;
    const __nv_bfloat16* Ag = g_exn + (size_t)m * BM * DDIM;
    const __nv_bfloat16* Bg = g_eyn + (size_t)n * BN * DDIM;

    // ---- writer addressing: 2 threads/row, 32B (2 swizzled 16B units) each ----
    const int l_row = tid >> 1;               // 0..127
    const int l_x = (l_row >> 1) & 3;         // swizzle key (64B rows)
    const int l_c0 = (tid & 1) * 2;           // first unit index (0 or 2)
    const uint32_t wA0 = sb + OFF_A + l_row * ROW_B + ((l_c0 ^ l_x) * 16);
    const uint32_t wB0 = sb + OFF_B + l_row * ROW_B + ((l_c0 ^ l_x) * 16);
    const __nv_bfloat16* gA0 = Ag + (size_t)l_row * DDIM + l_c0 * 8;
    const __nv_bfloat16* gB0 = Bg + (size_t)l_row * DDIM + l_c0 * 8;

    auto issue = [&](int chunk, int stage) {
        if (chunk < NKT) {
            const uint32_t da = wA0 + stage * STAGE_B;
            const uint32_t db = wB0 + stage * STAGE_B;
            const __nv_bfloat16* sa = gA0 + chunk * BK;
            const __nv_bfloat16* sbp = gB0 + chunk * BK;
            cpa16(da, sa);        cpa16(da ^ 16, sa + 8);
            cpa16(db, sbp);       cpa16(db ^ 16, sbp + 8);
        }
    };

    // ---- reader addressing (swizzle folded into base; kk toggle = XOR 32) ----
    const int lrow = lane & 15;
    const int h = lane >> 4;
    const uint32_t cx0 = ((h ^ ((lrow >> 1) & 3)) * 16);
    const uint32_t aBase = sb + OFF_A + (wm * 32 + lrow) * ROW_B + cx0;
    const uint32_t bBase = sb + OFF_B + (wn * 64 + lrow) * ROW_B + cx0;

    float acc[2][8][4];
#pragma unroll
    for (int mt = 0; mt < 2; mt++)
#pragma unroll
        for (int n8 = 0; n8 < 8; n8++)
#pragma unroll
            for (int r = 0; r < 4; r++) acc[mt][n8][r] = 0.f;

    auto compute = [&](int stage) {
#pragma unroll
        for (int kk = 0; kk < 2; ++kk) {
            uint32_t a[2][4], b[4][4];
#pragma unroll
            for (int mt = 0; mt < 2; mt++)
                ldsm4(a[mt], (aBase + stage * STAGE_B + mt * 1024) ^ (kk * 32));
#pragma unroll
            for (int n16 = 0; n16 < 4; n16++)
                ldsm4(b[n16], (bBase + stage * STAGE_B + n16 * 1024) ^ (kk * 32));
#pragma unroll
            for (int mt = 0; mt < 2; mt++)
#pragma unroll
                for (int n8 = 0; n8 < 8; n8++) {
                    const int n16 = n8 >> 1, sub = n8 & 1;
                    mma16816(acc[mt][n8], a[mt], b[n16][sub], b[n16][sub + 2]);
                }
        }
    };

    // prologue: 2 groups of 2 chunks
    issue(0, 0); issue(1, 1); cpa_commit();
    issue(2, 2); issue(3, 3); cpa_commit();

    // 12 supersteps, stage pattern period 3 -> unroll 3 (constant stages)
#pragma unroll 1
    for (int jo = 0; jo < 4; ++jo) {
        const int c0 = jo * 6;
        cpa_wait1(); __syncthreads();
        issue(c0 + 4, 4); issue(c0 + 5, 5); cpa_commit();
        compute(0); compute(1);
        cpa_wait1(); __syncthreads();
        issue(c0 + 6, 0); issue(c0 + 7, 1); cpa_commit();
        compute(2); compute(3);
        cpa_wait1(); __syncthreads();
        issue(c0 + 8, 2); issue(c0 + 9, 3); cpa_commit();
        compute(4); compute(5);
    }

    // ---- row-max epilogue ----
    float rm[2][2];
#pragma unroll
    for (int mt = 0; mt < 2; mt++) {
        float m0 = -1e30f, m1 = -1e30f;
#pragma unroll
        for (int n8 = 0; n8 < 8; n8++) {
            m0 = fmaxf(m0, fmaxf(acc[mt][n8][0], acc[mt][n8][1]));
            m1 = fmaxf(m1, fmaxf(acc[mt][n8][2], acc[mt][n8][3]));
        }
        rm[mt][0] = m0; rm[mt][1] = m1;
    }
    __syncthreads();
#pragma unroll
    for (int mt = 0; mt < 2; mt++) {
#pragma unroll
        for (int hh = 0; hh < 2; hh++) {
            float v = rm[mt][hh];
            v = fmaxf(v, __shfl_xor_sync(0xffffffffu, v, 1));
            v = fmaxf(v, __shfl_xor_sync(0xffffffffu, v, 2));
            if (tig == 0)
                red[wn * BM + wm * 32 + mt * 16 + hh * 8 + g] = v;
        }
    }
    __syncthreads();
    if (tid < BM) {
        const float v = fmaxf(red[tid], red[BM + tid]);
        atomicMax((int*)&out[m * BM + tid], __float_as_int(v));
    }
}

// ---------------------------------------------------------------------------
// launch
// ---------------------------------------------------------------------------
extern "C" void kernel_launch(void* const* d_in, const int* in_sizes, int n_in,
                              void* d_out, int out_size) {
    const float* ex = (const float*)d_in[0];
    const float* ey = (const float*)d_in[1];
    float* out = (float*)d_out;

    cudaFuncSetAttribute(chamfer_kernel, cudaFuncAttributeMaxDynamicSharedMemorySize,
                         SMEM_TOTAL);

    normalize_kernel<<<2048, 256>>>(ex, ey, out);
    chamfer_kernel<<<NMB * NNB, 256, SMEM_TOTAL>>>(out);
}